// round 3
// baseline (speedup 1.0000x reference)
#include <cuda_runtime.h>
#include <cuda_bf16.h>

#define G     500
#define DN    128
#define DE    64
#define DG    128
#define DO    128
#define NB_N  592            // node blocks
#define NB_E  592            // edge blocks
#define NBLK  (NB_N + NB_E)  // 1184 = 148 SMs * 8 blocks -> one wave

// Device scratch (no allocation allowed)
__device__ int   g_noff[G + 1];
__device__ int   g_eoff[G + 1];
__device__ float g_nagg[G * DN];   // raw sums; scaled in out_kernel
__device__ float g_eagg[G * DE];

// ---------------------------------------------------------------------------
// Kernel 0: parallel prefix scans (block 0 = nodes, block 1 = edges); all
// blocks zero the accumulator arrays for the atomic aggregation.
// ---------------------------------------------------------------------------
__global__ __launch_bounds__(512) void scan_zero_kernel(const int* __restrict__ nn,
                                                        const int* __restrict__ ne) {
    const int b = blockIdx.x, t = threadIdx.x;

    for (int i = b * 512 + t; i < G * DN; i += gridDim.x * 512) g_nagg[i] = 0.f;
    for (int i = b * 512 + t; i < G * DE; i += gridDim.x * 512) g_eagg[i] = 0.f;

    if (b < 2) {
        const int* len = (b == 0) ? nn : ne;
        int*       off = (b == 0) ? g_noff : g_eoff;
        const int lane = t & 31, w = t >> 5;

        int v = (t < G) ? len[t] : 0;
        #pragma unroll
        for (int d = 1; d < 32; d <<= 1) {
            int u = __shfl_up_sync(0xffffffffu, v, d);
            if (lane >= d) v += u;
        }
        __shared__ int wt[16];
        if (lane == 31) wt[w] = v;
        __syncthreads();
        if (w == 0) {
            int x = (lane < 16) ? wt[lane] : 0;
            #pragma unroll
            for (int d = 1; d < 16; d <<= 1) {
                int u = __shfl_up_sync(0xffffffffu, x, d);
                if (lane >= d) x += u;
            }
            if (lane < 16) wt[lane] = x;
        }
        __syncthreads();
        const int base = (w > 0) ? wt[w - 1] : 0;
        if (t < G) off[t + 1] = v + base;
        if (t == 0) off[0] = 0;
    }
}

// ---------------------------------------------------------------------------
// Kernel 1: flat segmented sum. Blocks [0,592) stream node rows, [592,1184)
// stream edge rows; each block owns one contiguous chunk of rows. Hot loop is
// pure float4 loads (unroll 4); per-thread graph boundary tracked in a
// register; atomicAdd flush only at boundaries and chunk end.
// ---------------------------------------------------------------------------
__global__ __launch_bounds__(256, 8) void agg_kernel(const float4* __restrict__ nf4,
                                                     const float4* __restrict__ ef4,
                                                     int Nrows, int Erows) {
    __shared__ int soff[G + 1];
    const int b    = blockIdx.x;
    const int tid  = threadIdx.x;
    const bool isn = (b < NB_N);

    const int* goff = isn ? g_noff : g_eoff;
    for (int i = tid; i <= G; i += 256) soff[i] = goff[i];
    __syncthreads();

    const int     C    = isn ? 32 : 16;        // float4 per row
    const int     rows = isn ? Nrows : Erows;
    const int     nb   = isn ? NB_N : NB_E;
    const int     bb   = isn ? b : b - NB_N;
    const float4* src  = isn ? nf4 : ef4;
    float*        agg  = isn ? g_nagg : g_eagg;
    const int     D    = C * 4;                // floats per row

    const int c0 = (int)((long long)rows * bb / nb);
    const int c1 = (int)((long long)rows * (bb + 1) / nb);

    const int lane   = tid & 31;
    const int w      = tid >> 5;
    const int col    = lane & (C - 1);
    const int sub    = lane / C;               // 0 (nodes) or 0/1 (edges)
    const int rpw    = 32 / C;                 // rows per warp per iter
    const int stride = 8 * rpw;                // rows per block per iter

    int r = c0 + w * rpw + sub;

    // binary search in smem: g such that soff[g] <= r < soff[g+1]
    int lo = 0, hi = G;
    while (lo < hi) {
        int mid = (lo + hi) >> 1;
        if (soff[mid + 1] <= r) lo = mid + 1; else hi = mid;
    }
    int g        = lo;
    int off_next = soff[g + 1];

    float4 acc = make_float4(0.f, 0.f, 0.f, 0.f);

    while (r < c1) {
        if (r >= off_next) {
            float* dst = agg + (size_t)g * D + col * 4;
            atomicAdd(dst + 0, acc.x);
            atomicAdd(dst + 1, acc.y);
            atomicAdd(dst + 2, acc.z);
            atomicAdd(dst + 3, acc.w);
            acc = make_float4(0.f, 0.f, 0.f, 0.f);
            do { g++; off_next = soff[g + 1]; } while (r >= off_next);
        }
        const int safe = min(c1, off_next);
        // unrolled MLP-4 hot loop (no branches, no barriers)
        for (; r + 3 * stride < safe; r += 4 * stride) {
            float4 v0 = __ldg(&src[(size_t)r * C + col]);
            float4 v1 = __ldg(&src[(size_t)(r + stride) * C + col]);
            float4 v2 = __ldg(&src[(size_t)(r + 2 * stride) * C + col]);
            float4 v3 = __ldg(&src[(size_t)(r + 3 * stride) * C + col]);
            acc.x += v0.x + v1.x + v2.x + v3.x;
            acc.y += v0.y + v1.y + v2.y + v3.y;
            acc.z += v0.z + v1.z + v2.z + v3.z;
            acc.w += v0.w + v1.w + v2.w + v3.w;
        }
        for (; r < safe; r += stride) {
            float4 v = __ldg(&src[(size_t)r * C + col]);
            acc.x += v.x; acc.y += v.y; acc.z += v.z; acc.w += v.w;
        }
    }

    float* dst = agg + (size_t)g * D + col * 4;
    atomicAdd(dst + 0, acc.x);
    atomicAdd(dst + 1, acc.y);
    atomicAdd(dst + 2, acc.z);
    atomicAdd(dst + 3, acc.w);
}

// ---------------------------------------------------------------------------
// Kernel 2: out[g][o] = <nsum[g],Wn[o]>/n + <esum[g],We[o]>/e
//                       + <gf[g],Wg[o]> + b[o]
// ---------------------------------------------------------------------------
__global__ __launch_bounds__(256) void out_kernel(const float* __restrict__ gf,
                                                  const float* __restrict__ Wn,
                                                  const float* __restrict__ We,
                                                  const float* __restrict__ Wg,
                                                  const float* __restrict__ bias,
                                                  float* __restrict__ out) {
    const int warp  = threadIdx.x >> 5;
    const int lane  = threadIdx.x & 31;
    const int gbase = blockIdx.x * 4;

    for (int t = warp; t < 4 * DO; t += 8) {
        const int g = gbase + (t >> 7);
        const int o = t & 127;

        const float inv_n = 1.0f / (float)max(g_noff[g + 1] - g_noff[g], 1);
        const float inv_e = 1.0f / (float)max(g_eoff[g + 1] - g_eoff[g], 1);

        float sn = 0.f, se = 0.f, sg = 0.f;

        const float* na = g_nagg + g * DN;
        const float* wn = Wn + o * DN;
        #pragma unroll
        for (int k = 0; k < DN / 32; k++) sn += na[lane + 32 * k] * wn[lane + 32 * k];

        const float* ea = g_eagg + g * DE;
        const float* we = We + o * DE;
        #pragma unroll
        for (int k = 0; k < DE / 32; k++) se += ea[lane + 32 * k] * we[lane + 32 * k];

        const float* ga = gf + g * DG;
        const float* wg = Wg + o * DG;
        #pragma unroll
        for (int k = 0; k < DG / 32; k++) sg += ga[lane + 32 * k] * wg[lane + 32 * k];

        float s = sn * inv_n + se * inv_e + sg;
        #pragma unroll
        for (int d = 16; d; d >>= 1) s += __shfl_xor_sync(0xffffffffu, s, d);

        if (lane == 0) out[g * DO + o] = s + bias[o];
    }
}

// ---------------------------------------------------------------------------
extern "C" void kernel_launch(void* const* d_in, const int* in_sizes, int n_in,
                              void* d_out, int out_size) {
    const float* node_features = (const float*)d_in[0];   // [N, 128]
    const float* edge_features = (const float*)d_in[1];   // [E, 64]
    const float* global_feats  = (const float*)d_in[2];   // [G, 128]
    const float* W_node        = (const float*)d_in[3];   // [128, 128]
    const float* W_edges       = (const float*)d_in[4];   // [128, 64]
    const float* W_global      = (const float*)d_in[5];   // [128, 128]
    const float* bias          = (const float*)d_in[6];   // [128]
    const int*   num_nodes     = (const int*)d_in[7];     // [G]
    const int*   num_edges     = (const int*)d_in[8];     // [G]
    float*       out           = (float*)d_out;           // [G, 128]

    const int Nrows = in_sizes[0] / DN;
    const int Erows = in_sizes[1] / DE;

    scan_zero_kernel<<<64, 512>>>(num_nodes, num_edges);
    agg_kernel<<<NBLK, 256>>>((const float4*)node_features,
                              (const float4*)edge_features, Nrows, Erows);
    out_kernel<<<(G + 3) / 4, 256>>>(global_feats, W_node, W_edges, W_global,
                                     bias, out);
}

// round 4
// speedup vs baseline: 1.3982x; 1.3982x over previous
#include <cuda_runtime.h>
#include <cuda_bf16.h>

#define G   500
#define DN  128
#define DE  64
#define DG  128
#define DO  128

// Device scratch (no allocation allowed)
__device__ int   g_noff[G + 1];
__device__ int   g_eoff[G + 1];
__device__ float g_nagg[G * DN];
__device__ float g_eagg[G * DE];

// ---------------------------------------------------------------------------
// Kernel 0: parallel prefix scans. Block 0 scans node lengths, block 1 scans
// edge lengths. Warp shuffle intra-warp scan + smem warp-total scan.
// ---------------------------------------------------------------------------
__global__ __launch_bounds__(512) void scan_kernel(const int* __restrict__ nn,
                                                   const int* __restrict__ ne) {
    const int b = blockIdx.x, t = threadIdx.x;
    const int* len = (b == 0) ? nn : ne;
    int*       off = (b == 0) ? g_noff : g_eoff;
    const int lane = t & 31, w = t >> 5;

    int v = (t < G) ? len[t] : 0;
    #pragma unroll
    for (int d = 1; d < 32; d <<= 1) {
        int u = __shfl_up_sync(0xffffffffu, v, d);
        if (lane >= d) v += u;
    }
    __shared__ int wt[16];
    if (lane == 31) wt[w] = v;
    __syncthreads();
    if (w == 0) {
        int x = (lane < 16) ? wt[lane] : 0;
        #pragma unroll
        for (int d = 1; d < 16; d <<= 1) {
            int u = __shfl_up_sync(0xffffffffu, x, d);
            if (lane >= d) x += u;
        }
        if (lane < 16) wt[lane] = x;
    }
    __syncthreads();
    const int base = (w > 0) ? wt[w - 1] : 0;
    if (t < G) off[t + 1] = v + base;
    if (t == 0) off[0] = 0;
}

// ---------------------------------------------------------------------------
// Kernel 1: fused node + edge segment-mean. Blocks [0,500) do node graphs,
// blocks [500,1000) do edge graphs. 512 threads, float4 coalesced loads.
// (R1 structure — best measured aggregation.)
// ---------------------------------------------------------------------------
__global__ __launch_bounds__(512) void agg_kernel(const float4* __restrict__ nf4,
                                                  const float4* __restrict__ ef4) {
    __shared__ float4 red[512];
    const int b   = blockIdx.x;
    const int tid = threadIdx.x;

    if (b < G) {
        // ---- node aggregation: 128 floats = 32 float4 per row ----
        const int lane = tid & 31;   // float4 column
        const int rg   = tid >> 5;   // 0..15 row group
        const int off0 = g_noff[b];
        const int off1 = g_noff[b + 1];
        const int n    = off1 - off0;
        const float4* base = nf4 + (size_t)off0 * 32 + lane;

        float4 acc = make_float4(0.f, 0.f, 0.f, 0.f);
        #pragma unroll 4
        for (int r = rg; r < n; r += 16) {
            float4 v = base[(size_t)r * 32];
            acc.x += v.x; acc.y += v.y; acc.z += v.z; acc.w += v.w;
        }
        red[rg * 32 + lane] = acc;
        __syncthreads();
        #pragma unroll
        for (int s = 8; s >= 1; s >>= 1) {
            if (rg < s) {
                float4 o = red[(rg + s) * 32 + lane];
                float4 m = red[rg * 32 + lane];
                m.x += o.x; m.y += o.y; m.z += o.z; m.w += o.w;
                red[rg * 32 + lane] = m;
            }
            __syncthreads();
        }
        if (rg == 0) {
            const float inv = 1.0f / (float)max(n, 1);
            float4 m = red[lane];
            m.x *= inv; m.y *= inv; m.z *= inv; m.w *= inv;
            reinterpret_cast<float4*>(g_nagg)[b * 32 + lane] = m;
        }
    } else {
        // ---- edge aggregation: 64 floats = 16 float4 per row ----
        const int g    = b - G;
        const int lane = tid & 15;   // float4 column
        const int rg   = tid >> 4;   // 0..31 row group
        const int off0 = g_eoff[g];
        const int off1 = g_eoff[g + 1];
        const int n    = off1 - off0;
        const float4* base = ef4 + (size_t)off0 * 16 + lane;

        float4 acc = make_float4(0.f, 0.f, 0.f, 0.f);
        #pragma unroll 4
        for (int r = rg; r < n; r += 32) {
            float4 v = base[(size_t)r * 16];
            acc.x += v.x; acc.y += v.y; acc.z += v.z; acc.w += v.w;
        }
        red[rg * 16 + lane] = acc;
        __syncthreads();
        #pragma unroll
        for (int s = 16; s >= 1; s >>= 1) {
            if (rg < s) {
                float4 o = red[(rg + s) * 16 + lane];
                float4 m = red[rg * 16 + lane];
                m.x += o.x; m.y += o.y; m.z += o.z; m.w += o.w;
                red[rg * 16 + lane] = m;
            }
            __syncthreads();
        }
        if (rg == 0) {
            const float inv = 1.0f / (float)max(n, 1);
            float4 m = red[lane];
            m.x *= inv; m.y *= inv; m.z *= inv; m.w *= inv;
            reinterpret_cast<float4*>(g_eagg)[g * 16 + lane] = m;
        }
    }
}

// ---------------------------------------------------------------------------
// Kernel 2: out[g][o] = <nagg[g],Wn[o]> + <eagg[g],We[o]> + <gf[g],Wg[o]> + b[o]
// One warp per (g,o) task; coalesced W reads; butterfly reduce.
// ---------------------------------------------------------------------------
__global__ __launch_bounds__(256) void out_kernel(const float* __restrict__ gf,
                                                  const float* __restrict__ Wn,
                                                  const float* __restrict__ We,
                                                  const float* __restrict__ Wg,
                                                  const float* __restrict__ bias,
                                                  float* __restrict__ out) {
    const int warp  = threadIdx.x >> 5;  // 0..7
    const int lane  = threadIdx.x & 31;
    const int gbase = blockIdx.x * 4;

    for (int t = warp; t < 4 * DO; t += 8) {
        const int g = gbase + (t >> 7);
        const int o = t & 127;
        float s = 0.f;

        const float* na = g_nagg + g * DN;
        const float* wn = Wn + o * DN;
        #pragma unroll
        for (int k = 0; k < DN / 32; k++) s += na[lane + 32 * k] * wn[lane + 32 * k];

        const float* ea = g_eagg + g * DE;
        const float* we = We + o * DE;
        #pragma unroll
        for (int k = 0; k < DE / 32; k++) s += ea[lane + 32 * k] * we[lane + 32 * k];

        const float* ga = gf + g * DG;
        const float* wg = Wg + o * DG;
        #pragma unroll
        for (int k = 0; k < DG / 32; k++) s += ga[lane + 32 * k] * wg[lane + 32 * k];

        #pragma unroll
        for (int d = 16; d; d >>= 1) s += __shfl_xor_sync(0xffffffffu, s, d);

        if (lane == 0) out[g * DO + o] = s + bias[o];
    }
}

// ---------------------------------------------------------------------------
extern "C" void kernel_launch(void* const* d_in, const int* in_sizes, int n_in,
                              void* d_out, int out_size) {
    const float* node_features = (const float*)d_in[0];   // [N, 128]
    const float* edge_features = (const float*)d_in[1];   // [E, 64]
    const float* global_feats  = (const float*)d_in[2];   // [G, 128]
    const float* W_node        = (const float*)d_in[3];   // [128, 128]
    const float* W_edges       = (const float*)d_in[4];   // [128, 64]
    const float* W_global      = (const float*)d_in[5];   // [128, 128]
    const float* bias          = (const float*)d_in[6];   // [128]
    const int*   num_nodes     = (const int*)d_in[7];     // [G]
    const int*   num_edges     = (const int*)d_in[8];     // [G]
    float*       out           = (float*)d_out;           // [G, 128]

    scan_kernel<<<2, 512>>>(num_nodes, num_edges);
    agg_kernel<<<2 * G, 512>>>((const float4*)node_features,
                               (const float4*)edge_features);
    out_kernel<<<(G + 3) / 4, 256>>>(global_feats, W_node, W_edges, W_global,
                                     bias, out);
}

// round 6
// speedup vs baseline: 1.9141x; 1.3690x over previous
#include <cuda_runtime.h>
#include <cuda_bf16.h>

#define G   500
#define DN  128
#define DE  64
#define DG  128
#define DO  128

// ---------------------------------------------------------------------------
// One block per graph: compute segment offsets (block-local reduce of length
// arrays), stream node rows + edge rows (float4 coalesced, R1-proven loop),
// tree-reduce to smem means, then project 128 outputs in-block.
// ---------------------------------------------------------------------------
__global__ __launch_bounds__(512) void fused_kernel(const float4* __restrict__ nf4,
                                                    const float4* __restrict__ ef4,
                                                    const float*  __restrict__ gf,
                                                    const float*  __restrict__ Wn,
                                                    const float*  __restrict__ We,
                                                    const float*  __restrict__ Wg,
                                                    const float*  __restrict__ bias,
                                                    const int*    __restrict__ nn,
                                                    const int*    __restrict__ ne,
                                                    float*        __restrict__ out) {
    __shared__ float4 red[512];
    __shared__ float  nagg_s[DN];
    __shared__ float  eagg_s[DE];
    __shared__ int    sint[34];   // [0..15] node partials, [16..31] edge
                                  // partials, [32] node total, [33] edge total

    const int g    = blockIdx.x;
    const int tid  = threadIdx.x;
    const int lane = tid & 31;
    const int w    = tid >> 5;

    // ---- offsets: sum lengths[0..g) for nodes and edges (G <= 512) ----
    int pn = 0, pe = 0;
    if (tid < g) { pn = nn[tid]; pe = ne[tid]; }
    #pragma unroll
    for (int d = 16; d; d >>= 1) {
        pn += __shfl_xor_sync(0xffffffffu, pn, d);
        pe += __shfl_xor_sync(0xffffffffu, pe, d);
    }
    if (lane == 0) { sint[w] = pn; sint[16 + w] = pe; }
    __syncthreads();
    // stage 2: warps 0/1 reduce the 16 partials; results go to DEDICATED
    // slots 32/33 (disjoint from the partials being read -> no race).
    if (w == 0) {
        int a = (lane < 16) ? sint[lane] : 0;
        #pragma unroll
        for (int d = 8; d; d >>= 1) a += __shfl_xor_sync(0xffffffffu, a, d);
        if (lane == 0) sint[32] = a;
    } else if (w == 1) {
        int a = (lane < 16) ? sint[16 + lane] : 0;
        #pragma unroll
        for (int d = 8; d; d >>= 1) a += __shfl_xor_sync(0xffffffffu, a, d);
        if (lane == 0) sint[33] = a;
    }
    __syncthreads();
    const int noff = sint[32];
    const int eoff = sint[33];
    const int ncnt = nn[g];
    const int ecnt = ne[g];

    // ---- node streaming: 32 float4 cols x 16 row-groups ----
    {
        const float4* base = nf4 + (size_t)noff * 32 + lane;
        float4 acc = make_float4(0.f, 0.f, 0.f, 0.f);
        #pragma unroll 4
        for (int r = w; r < ncnt; r += 16) {
            float4 v = base[(size_t)r * 32];
            acc.x += v.x; acc.y += v.y; acc.z += v.z; acc.w += v.w;
        }
        red[w * 32 + lane] = acc;
        __syncthreads();
        #pragma unroll
        for (int s = 8; s >= 1; s >>= 1) {
            if (w < s) {
                float4 o = red[(w + s) * 32 + lane];
                float4 m = red[w * 32 + lane];
                m.x += o.x; m.y += o.y; m.z += o.z; m.w += o.w;
                red[w * 32 + lane] = m;
            }
            __syncthreads();
        }
        if (w == 0) {
            const float inv = 1.0f / (float)max(ncnt, 1);
            float4 m = red[lane];
            nagg_s[lane * 4 + 0] = m.x * inv;
            nagg_s[lane * 4 + 1] = m.y * inv;
            nagg_s[lane * 4 + 2] = m.z * inv;
            nagg_s[lane * 4 + 3] = m.w * inv;
        }
        __syncthreads();
    }

    // ---- edge streaming: 16 float4 cols x 32 row-groups ----
    {
        const int col = tid & 15;
        const int rg  = tid >> 4;
        const float4* base = ef4 + (size_t)eoff * 16 + col;
        float4 acc = make_float4(0.f, 0.f, 0.f, 0.f);
        #pragma unroll 4
        for (int r = rg; r < ecnt; r += 32) {
            float4 v = base[(size_t)r * 16];
            acc.x += v.x; acc.y += v.y; acc.z += v.z; acc.w += v.w;
        }
        red[rg * 16 + col] = acc;
        __syncthreads();
        #pragma unroll
        for (int s = 16; s >= 1; s >>= 1) {
            if (rg < s) {
                float4 o = red[(rg + s) * 16 + col];
                float4 m = red[rg * 16 + col];
                m.x += o.x; m.y += o.y; m.z += o.z; m.w += o.w;
                red[rg * 16 + col] = m;
            }
            __syncthreads();
        }
        if (rg == 0) {
            const float inv = 1.0f / (float)max(ecnt, 1);
            float4 m = red[col];
            eagg_s[col * 4 + 0] = m.x * inv;
            eagg_s[col * 4 + 1] = m.y * inv;
            eagg_s[col * 4 + 2] = m.z * inv;
            eagg_s[col * 4 + 3] = m.w * inv;
        }
        __syncthreads();
    }

    // ---- projection: 16 warps x 8 outputs each ----
    const float* gfr = gf + (size_t)g * DG;
    for (int o = w; o < DO; o += 16) {
        float s = 0.f;
        const float* wn = Wn + o * DN;
        #pragma unroll
        for (int k = 0; k < DN / 32; k++) s += nagg_s[lane + 32 * k] * wn[lane + 32 * k];
        const float* we = We + o * DE;
        #pragma unroll
        for (int k = 0; k < DE / 32; k++) s += eagg_s[lane + 32 * k] * we[lane + 32 * k];
        const float* wgp = Wg + o * DG;
        #pragma unroll
        for (int k = 0; k < DG / 32; k++) s += gfr[lane + 32 * k] * wgp[lane + 32 * k];
        #pragma unroll
        for (int d = 16; d; d >>= 1) s += __shfl_xor_sync(0xffffffffu, s, d);
        if (lane == 0) out[(size_t)g * DO + o] = s + bias[o];
    }
}

// ---------------------------------------------------------------------------
extern "C" void kernel_launch(void* const* d_in, const int* in_sizes, int n_in,
                              void* d_out, int out_size) {
    const float* node_features = (const float*)d_in[0];   // [N, 128]
    const float* edge_features = (const float*)d_in[1];   // [E, 64]
    const float* global_feats  = (const float*)d_in[2];   // [G, 128]
    const float* W_node        = (const float*)d_in[3];   // [128, 128]
    const float* W_edges       = (const float*)d_in[4];   // [128, 64]
    const float* W_global      = (const float*)d_in[5];   // [128, 128]
    const float* bias          = (const float*)d_in[6];   // [128]
    const int*   num_nodes     = (const int*)d_in[7];     // [G]
    const int*   num_edges     = (const int*)d_in[8];     // [G]
    float*       out           = (float*)d_out;           // [G, 128]

    fused_kernel<<<G, 512>>>((const float4*)node_features,
                             (const float4*)edge_features,
                             global_feats, W_node, W_edges, W_global, bias,
                             num_nodes, num_edges, out);
}